// round 3
// baseline (speedup 1.0000x reference)
#include <cuda_runtime.h>
#include <cuda_bf16.h>
#include <cstdint>

// Problem dims
#define N_LINK 2000
#define N_FLOW 30000
#define N_PATH 50000
#define E1 120000
#define E2 120000
#define HID 256
#define NH 4
#define HD 256   // per-head dim
#define HDTOT 1024  // NH*HD

// ---------------- scratch (static device arrays; no runtime alloc) ------------
__device__ float g_hlink[N_LINK * HID];
__device__ float g_hflow[N_FLOW * HID];
__device__ float g_hp0[N_PATH * HID];
__device__ float g_hp1[N_PATH * HID];   // h_path after conv1 == x_res1
__device__ float g_hp2[N_PATH * HID];   // h_path after conv2 == x_res2
__device__ float g_z[N_FLOW * HDTOT];   // z_src scratch (covers both convs)
__device__ float g_aggm[N_PATH * HID];  // head-meaned aggregation
__device__ float g_x1[N_PATH * HID];    // decoder hidden
__device__ float g_vl[HID * NH];
__device__ float g_vr[HID * NH];
__device__ float g_ce[NH];
__device__ float g_el[N_FLOW * NH];
__device__ float g_er[N_PATH * NH];
__device__ float g_elog[E1 * NH];       // edge logits -> exp numerators
__device__ unsigned g_maxenc[N_PATH * NH];
__device__ float g_denom[N_PATH * NH];

// order-preserving float<->uint for atomicMax
__device__ __forceinline__ unsigned fenc(float x) {
    unsigned b = __float_as_uint(x);
    return (b & 0x80000000u) ? ~b : (b | 0x80000000u);
}
__device__ __forceinline__ float fdec(unsigned u) {
    unsigned b = (u & 0x80000000u) ? (u & 0x7FFFFFFFu) : ~u;
    return __uint_as_float(b);
}
#define ENC_NEG_INF 0x007FFFFFu  // fenc(-inf)

// ---------------- kernels ----------------------------------------------------

// out[n, 0:256] = relu(x[n, 0:K] @ W[K,256] + b); one row per block
template <int K>
__global__ void proj_kernel(const float* __restrict__ x, const float* __restrict__ W,
                            const float* __restrict__ b, float* __restrict__ out, int N) {
    __shared__ float xs[K];
    int n = blockIdx.x;
    if (n >= N) return;
    int j = threadIdx.x;
    if (j < K) xs[j] = x[n * K + j];
    __syncthreads();
    float acc = b[j];
#pragma unroll
    for (int k = 0; k < K; k++) acc = fmaf(xs[k], W[k * HID + j], acc);
    out[n * HID + j] = fmaxf(acc, 0.0f);
}

// v[k*NH+h] = sum_d fc[k*1024 + h*256 + d] * attn[h*256 + d]
// grid.x = number of k rows (HID, or 1 for fc_e1); block = 128 (warp per head)
__global__ void attnvec_kernel(const float* __restrict__ fc, const float* __restrict__ attn,
                               float* __restrict__ v) {
    int k = blockIdx.x;
    int h = threadIdx.x >> 5;
    int lane = threadIdx.x & 31;
    float s = 0.f;
    const float* fr = fc + (size_t)k * HDTOT + h * HD;
    const float* ar = attn + h * HD;
    for (int d = lane; d < HD; d += 32) s = fmaf(fr[d], ar[d], s);
#pragma unroll
    for (int o = 16; o; o >>= 1) s += __shfl_xor_sync(0xffffffffu, s, o);
    if (lane == 0) v[k * NH + h] = s;
}

// out[n*NH+h] = h_src[n,:] @ v[:,h]; block=128 (warp per head), grid=N
__global__ void dotvec_kernel(const float* __restrict__ hsrc, const float* __restrict__ v,
                              float* __restrict__ out, int N) {
    int n = blockIdx.x;
    if (n >= N) return;
    int h = threadIdx.x >> 5;
    int lane = threadIdx.x & 31;
    const float* hr = hsrc + (size_t)n * HID;
    float s = 0.f;
    for (int k = lane; k < HID; k += 32) s = fmaf(hr[k], v[k * NH + h], s);
#pragma unroll
    for (int o = 16; o; o >>= 1) s += __shfl_xor_sync(0xffffffffu, s, o);
    if (lane == 0) out[n * NH + h] = s;
}

__global__ void init_seg_kernel(unsigned* __restrict__ maxenc, float* __restrict__ denom, int n) {
    int i = blockIdx.x * blockDim.x + threadIdx.x;
    if (i < n) { maxenc[i] = ENC_NEG_INF; denom[i] = 0.f; }
}

// pass A: edge logits (leaky-relu) + segment max
__global__ void edge_logits_kernel(const int* __restrict__ src, const int* __restrict__ dst,
                                   const float* __restrict__ el, const float* __restrict__ er,
                                   const float* __restrict__ e2p, const float* __restrict__ ce,
                                   float* __restrict__ elog, unsigned* __restrict__ maxenc,
                                   int E, int use_ee) {
    int i = blockIdx.x * blockDim.x + threadIdx.x;
    if (i >= E * NH) return;
    int e = i >> 2, h = i & 3;
    int s = src[e], t = dst[e];
    float v = el[s * NH + h] + er[t * NH + h];
    if (use_ee) v = fmaf(e2p[e], ce[h], v);
    v = (v > 0.f) ? v : 0.2f * v;
    elog[i] = v;
    atomicMax(&maxenc[t * NH + h], fenc(v));
}

// pass B: numerator exp + segment sum
__global__ void edge_exp_kernel(const int* __restrict__ dst, float* __restrict__ elog,
                                const unsigned* __restrict__ maxenc, float* __restrict__ denom,
                                int E) {
    int i = blockIdx.x * blockDim.x + threadIdx.x;
    if (i >= E * NH) return;
    int e = i >> 2, h = i & 3;
    int t = dst[e];
    float m = fdec(maxenc[t * NH + h]);
    float a = expf(elog[i] - m);
    elog[i] = a;
    atomicAdd(&denom[t * NH + h], a);
}

// pass C: aggregate (head mean fused): aggm[t,d] += 0.25 * sum_h alpha[e,h]*z[s,h,d]
// one edge per block, 256 threads (one d each)
__global__ void aggregate_kernel(const int* __restrict__ src, const int* __restrict__ dst,
                                 const float* __restrict__ anum, const float* __restrict__ denom,
                                 const float* __restrict__ z, float* __restrict__ aggm, int E) {
    int e = blockIdx.x;
    if (e >= E) return;
    int s = src[e], t = dst[e];
    __shared__ float al[NH];
    if (threadIdx.x < NH) {
        float dn = denom[t * NH + threadIdx.x];
        al[threadIdx.x] = anum[e * NH + threadIdx.x] / fmaxf(dn, 1e-9f) * 0.25f;
    }
    __syncthreads();
    int d = threadIdx.x;
    const float* zr = z + (size_t)s * HDTOT;
    float v = al[0] * zr[d] + al[1] * zr[HD + d] + al[2] * zr[2 * HD + d] + al[3] * zr[3 * HD + d];
    atomicAdd(&aggm[(size_t)t * HID + d], v);
}

// ---------------- SGEMM: C = op(A[M,K] @ B[K,N] (+C) (+addv) (+bias), relu?) ---
#define BM 64
#define BN 64
#define BK 16
#define FLAG_RELU 1
#define FLAG_ACC 2

__global__ __launch_bounds__(256) void sgemm_kernel(
    const float* __restrict__ A, const float* __restrict__ B, float* __restrict__ C,
    int M, int N, int K,
    const float* __restrict__ addv, const float* __restrict__ bias, int flags) {
    __shared__ float As[BK][BM + 1];
    __shared__ float Bs[BK][BN];
    int bm = blockIdx.y * BM;
    int bn = blockIdx.x * BN;
    int t = threadIdx.x;

    int arow = t >> 2;          // 0..63
    int acol = (t & 3) * 4;     // 0,4,8,12
    int brow = t >> 4;          // 0..15
    int bcol = (t & 15) * 4;    // 0..60

    int tm = (t >> 4) * 4;
    int tn = (t & 15) * 4;
    float acc[4][4] = {};

    for (int k0 = 0; k0 < K; k0 += BK) {
        float4 av;
        if (bm + arow < M)
            av = *(const float4*)(A + (size_t)(bm + arow) * K + k0 + acol);
        else
            av = make_float4(0.f, 0.f, 0.f, 0.f);
        As[acol + 0][arow] = av.x;
        As[acol + 1][arow] = av.y;
        As[acol + 2][arow] = av.z;
        As[acol + 3][arow] = av.w;
        float4 bv = *(const float4*)(B + (size_t)(k0 + brow) * N + bn + bcol);
        *(float4*)(&Bs[brow][bcol]) = bv;
        __syncthreads();
#pragma unroll
        for (int kk = 0; kk < BK; kk++) {
            float a[4], b[4];
#pragma unroll
            for (int i = 0; i < 4; i++) a[i] = As[kk][tm + i];
#pragma unroll
            for (int j = 0; j < 4; j++) b[j] = Bs[kk][tn + j];
#pragma unroll
            for (int i = 0; i < 4; i++)
#pragma unroll
                for (int j = 0; j < 4; j++) acc[i][j] = fmaf(a[i], b[j], acc[i][j]);
        }
        __syncthreads();
    }
#pragma unroll
    for (int i = 0; i < 4; i++) {
        int m = bm + tm + i;
        if (m >= M) continue;
#pragma unroll
        for (int j = 0; j < 4; j++) {
            int n = bn + tn + j;
            float v = acc[i][j];
            size_t idx = (size_t)m * N + n;
            if (flags & FLAG_ACC) v += C[idx];
            if (addv) v += addv[idx];
            if (bias) v += bias[n];
            if (flags & FLAG_RELU) v = fmaxf(v, 0.f);
            C[idx] = v;
        }
    }
}

// final: out[n,0:2] = x1[n,:]@W2[256,2] + b2 ; warp per row
__global__ void final_kernel(const float* __restrict__ x1, const float* __restrict__ W2,
                             const float* __restrict__ b2, float* __restrict__ out, int N) {
    int warp = (blockIdx.x * blockDim.x + threadIdx.x) >> 5;
    int lane = threadIdx.x & 31;
    if (warp >= N) return;
    const float* xr = x1 + (size_t)warp * HID;
    float s0 = 0.f, s1 = 0.f;
    for (int k = lane; k < HID; k += 32) {
        float xv = xr[k];
        s0 = fmaf(xv, W2[k * 2 + 0], s0);
        s1 = fmaf(xv, W2[k * 2 + 1], s1);
    }
#pragma unroll
    for (int o = 16; o; o >>= 1) {
        s0 += __shfl_xor_sync(0xffffffffu, s0, o);
        s1 += __shfl_xor_sync(0xffffffffu, s1, o);
    }
    if (lane == 0) {
        out[warp * 2 + 0] = s0 + b2[0];
        out[warp * 2 + 1] = s1 + b2[1];
    }
}

// ---------------- host launcher ----------------------------------------------
static inline void* sym(const void* s) {
    void* p = nullptr;
    cudaGetSymbolAddress(&p, s);
    return p;
}

extern "C" void kernel_launch(void* const* d_in, const int* in_sizes, int n_in,
                              void* d_out, int out_size) {
    const float* x_link = (const float*)d_in[0];
    const float* x_flow = (const float*)d_in[1];
    const float* x_path = (const float*)d_in[2];
    const float* e2p = (const float*)d_in[3];
    const float* Wp_link = (const float*)d_in[4];
    const float* bp_link = (const float*)d_in[5];
    const float* Wp_flow = (const float*)d_in[6];
    const float* bp_flow = (const float*)d_in[7];
    const float* Wp_path = (const float*)d_in[8];
    const float* bp_path = (const float*)d_in[9];
    const float* fc_src1 = (const float*)d_in[10];
    const float* fc_dst1 = (const float*)d_in[11];
    const float* fc_e1 = (const float*)d_in[12];
    const float* attn_l1 = (const float*)d_in[13];
    const float* attn_r1 = (const float*)d_in[14];
    const float* attn_e1 = (const float*)d_in[15];
    const float* res_W1 = (const float*)d_in[16];
    const float* fc_src2 = (const float*)d_in[17];
    const float* fc_dst2 = (const float*)d_in[18];
    const float* attn_l2 = (const float*)d_in[19];
    const float* attn_r2 = (const float*)d_in[20];
    const float* res_W2 = (const float*)d_in[21];
    const float* W1 = (const float*)d_in[22];
    const float* b1 = (const float*)d_in[23];
    const float* W2 = (const float*)d_in[24];
    const float* b2 = (const float*)d_in[25];
    const int* src1 = (const int*)d_in[26];
    const int* dst1 = (const int*)d_in[27];
    const int* src2 = (const int*)d_in[28];
    const int* dst2 = (const int*)d_in[29];
    float* out = (float*)d_out;

    float* hlink = (float*)sym(g_hlink);
    float* hflow = (float*)sym(g_hflow);
    float* hp0 = (float*)sym(g_hp0);
    float* hp1 = (float*)sym(g_hp1);
    float* hp2 = (float*)sym(g_hp2);
    float* z = (float*)sym(g_z);
    float* aggm = (float*)sym(g_aggm);
    float* x1 = (float*)sym(g_x1);
    float* vl = (float*)sym(g_vl);
    float* vr = (float*)sym(g_vr);
    float* ce = (float*)sym(g_ce);
    float* el = (float*)sym(g_el);
    float* er = (float*)sym(g_er);
    float* elog = (float*)sym(g_elog);
    unsigned* maxenc = (unsigned*)sym(g_maxenc);
    float* denom = (float*)sym(g_denom);

    // 1) per-type projections
    proj_kernel<8><<<N_LINK, HID>>>(x_link, Wp_link, bp_link, hlink, N_LINK);
    proj_kernel<16><<<N_FLOW, HID>>>(x_flow, Wp_flow, bp_flow, hflow, N_FLOW);
    proj_kernel<8><<<N_PATH, HID>>>(x_path, Wp_path, bp_path, hp0, N_PATH);

    dim3 gz1(HDTOT / BN, (N_LINK + BM - 1) / BM);
    dim3 gz2(HDTOT / BN, (N_FLOW + BM - 1) / BM);
    dim3 gres(HID / BN, (N_PATH + BM - 1) / BM);

    // ====================== conv1: link -> path ======================
    attnvec_kernel<<<HID, 128>>>(fc_src1, attn_l1, vl);
    attnvec_kernel<<<HID, 128>>>(fc_dst1, attn_r1, vr);
    attnvec_kernel<<<1, 128>>>(fc_e1, attn_e1, ce);

    sgemm_kernel<<<gz1, 256>>>(hlink, fc_src1, z, N_LINK, HDTOT, HID, nullptr, nullptr, 0);
    dotvec_kernel<<<N_LINK, 128>>>(hlink, vl, el, N_LINK);
    dotvec_kernel<<<N_PATH, 128>>>(hp0, vr, er, N_PATH);

    init_seg_kernel<<<(N_PATH * NH + 255) / 256, 256>>>(maxenc, denom, N_PATH * NH);
    cudaMemsetAsync(aggm, 0, (size_t)N_PATH * HID * sizeof(float));

    edge_logits_kernel<<<(E1 * NH + 255) / 256, 256>>>(src1, dst1, el, er, e2p, ce, elog, maxenc, E1, 1);
    edge_exp_kernel<<<(E1 * NH + 255) / 256, 256>>>(dst1, elog, maxenc, denom, E1);
    aggregate_kernel<<<E1, HID>>>(src1, dst1, elog, denom, z, aggm, E1);

    // hp1 = relu(aggm + hp0 @ res_W1)   (== x_res1 == h_path after conv1)
    sgemm_kernel<<<gres, 256>>>(hp0, res_W1, hp1, N_PATH, HID, HID, aggm, nullptr, FLAG_RELU);

    // ====================== conv2: flow -> path ======================
    attnvec_kernel<<<HID, 128>>>(fc_src2, attn_l2, vl);
    attnvec_kernel<<<HID, 128>>>(fc_dst2, attn_r2, vr);

    sgemm_kernel<<<gz2, 256>>>(hflow, fc_src2, z, N_FLOW, HDTOT, HID, nullptr, nullptr, 0);
    dotvec_kernel<<<N_FLOW, 128>>>(hflow, vl, el, N_FLOW);
    dotvec_kernel<<<N_PATH, 128>>>(hp1, vr, er, N_PATH);

    init_seg_kernel<<<(N_PATH * NH + 255) / 256, 256>>>(maxenc, denom, N_PATH * NH);
    cudaMemsetAsync(aggm, 0, (size_t)N_PATH * HID * sizeof(float));

    edge_logits_kernel<<<(E2 * NH + 255) / 256, 256>>>(src2, dst2, el, er, nullptr, ce, elog, maxenc, E2, 0);
    edge_exp_kernel<<<(E2 * NH + 255) / 256, 256>>>(dst2, elog, maxenc, denom, E2);
    aggregate_kernel<<<E2, HID>>>(src2, dst2, elog, denom, z, aggm, E2);

    // hp2 = relu(aggm + hp1 @ res_W2)   (== x_res2 == final h_path)
    sgemm_kernel<<<gres, 256>>>(hp1, res_W2, hp2, N_PATH, HID, HID, aggm, nullptr, FLAG_RELU);

    // ====================== decoder ======================
    // x = concat(hp2, hp1, hp2); x1 = relu(x @ W1 + b1) as three accumulating GEMMs
    sgemm_kernel<<<gres, 256>>>(hp2, W1, x1, N_PATH, HID, HID, nullptr, nullptr, 0);
    sgemm_kernel<<<gres, 256>>>(hp1, W1 + 256 * 256, x1, N_PATH, HID, HID, nullptr, nullptr, FLAG_ACC);
    sgemm_kernel<<<gres, 256>>>(hp2, W1 + 512 * 256, x1, N_PATH, HID, HID, nullptr, b1, FLAG_ACC | FLAG_RELU);

    // out = x1 @ W2 + b2
    final_kernel<<<(N_PATH * 32 + 255) / 256, 256>>>(x1, W2, b2, out, N_PATH);
}

// round 4
// speedup vs baseline: 1.3356x; 1.3356x over previous
#include <cuda_runtime.h>
#include <cuda_bf16.h>
#include <cstdint>

// Problem dims
#define N_LINK 2000
#define N_FLOW 30000
#define N_PATH 50000
#define E1 120000
#define E2 120000
#define HID 256
#define NH 4
#define HD 256      // per-head dim
#define HDTOT 1024  // NH*HD

// ---------------- scratch (static device arrays; no runtime alloc) ------------
__device__ float g_hlink[N_LINK * HID];
__device__ float g_hflow[N_FLOW * HID];
__device__ float g_hp0[N_PATH * HID];
__device__ float g_hp1[N_PATH * HID];   // h_path after conv1 == x_res1
__device__ float g_hp2[N_PATH * HID];   // h_path after conv2 == x_res2
__device__ float g_z[N_FLOW * HDTOT];   // z_src scratch (covers both convs)
__device__ float g_aggm[N_PATH * HID];  // head-meaned aggregation
__device__ float g_x1[N_PATH * HID];    // decoder hidden
__device__ float g_vl[HID * NH];
__device__ float g_vr[HID * NH];
__device__ float g_ce[NH];
__device__ float g_el[N_FLOW * NH];
__device__ float g_er[N_PATH * NH];
__device__ float g_elog[E1 * NH];       // edge logits -> exp numerators
__device__ unsigned g_maxenc[N_PATH * NH];
__device__ float g_denom[N_PATH * NH];

// order-preserving float<->uint for atomicMax
__device__ __forceinline__ unsigned fenc(float x) {
    unsigned b = __float_as_uint(x);
    return (b & 0x80000000u) ? ~b : (b | 0x80000000u);
}
__device__ __forceinline__ float fdec(unsigned u) {
    unsigned b = (u & 0x80000000u) ? (u & 0x7FFFFFFFu) : ~u;
    return __uint_as_float(b);
}
#define ENC_NEG_INF 0x007FFFFFu  // fenc(-inf)

// ---------------- small kernels ----------------------------------------------

template <int K>
__global__ void proj_kernel(const float* __restrict__ x, const float* __restrict__ W,
                            const float* __restrict__ b, float* __restrict__ out, int N) {
    __shared__ float xs[K];
    int n = blockIdx.x;
    if (n >= N) return;
    int j = threadIdx.x;
    if (j < K) xs[j] = x[n * K + j];
    __syncthreads();
    float acc = b[j];
#pragma unroll
    for (int k = 0; k < K; k++) acc = fmaf(xs[k], W[k * HID + j], acc);
    out[n * HID + j] = fmaxf(acc, 0.0f);
}

// v[k*NH+h] = sum_d fc[k*1024 + h*256 + d] * attn[h*256 + d]
__global__ void attnvec_kernel(const float* __restrict__ fc, const float* __restrict__ attn,
                               float* __restrict__ v) {
    int k = blockIdx.x;
    int h = threadIdx.x >> 5;
    int lane = threadIdx.x & 31;
    float s = 0.f;
    const float* fr = fc + (size_t)k * HDTOT + h * HD;
    const float* ar = attn + h * HD;
    for (int d = lane; d < HD; d += 32) s = fmaf(fr[d], ar[d], s);
#pragma unroll
    for (int o = 16; o; o >>= 1) s += __shfl_xor_sync(0xffffffffu, s, o);
    if (lane == 0) v[k * NH + h] = s;
}

// out[n*NH+h] = h_src[n,:] @ v[:,h]
__global__ void dotvec_kernel(const float* __restrict__ hsrc, const float* __restrict__ v,
                              float* __restrict__ out, int N) {
    int n = blockIdx.x;
    if (n >= N) return;
    int h = threadIdx.x >> 5;
    int lane = threadIdx.x & 31;
    const float* hr = hsrc + (size_t)n * HID;
    float s = 0.f;
    for (int k = lane; k < HID; k += 32) s = fmaf(hr[k], v[k * NH + h], s);
#pragma unroll
    for (int o = 16; o; o >>= 1) s += __shfl_xor_sync(0xffffffffu, s, o);
    if (lane == 0) out[n * NH + h] = s;
}

__global__ void init_seg_kernel(unsigned* __restrict__ maxenc, float* __restrict__ denom, int n) {
    int i = blockIdx.x * blockDim.x + threadIdx.x;
    if (i < n) { maxenc[i] = ENC_NEG_INF; denom[i] = 0.f; }
}

// pass A: edge logits (leaky-relu) + segment max
__global__ void edge_logits_kernel(const int* __restrict__ src, const int* __restrict__ dst,
                                   const float* __restrict__ el, const float* __restrict__ er,
                                   const float* __restrict__ e2p, const float* __restrict__ ce,
                                   float* __restrict__ elog, unsigned* __restrict__ maxenc,
                                   int E, int use_ee) {
    int i = blockIdx.x * blockDim.x + threadIdx.x;
    if (i >= E * NH) return;
    int e = i >> 2, h = i & 3;
    int s = src[e], t = dst[e];
    float v = el[s * NH + h] + er[t * NH + h];
    if (use_ee) v = fmaf(e2p[e], ce[h], v);
    v = (v > 0.f) ? v : 0.2f * v;
    elog[i] = v;
    atomicMax(&maxenc[t * NH + h], fenc(v));
}

// pass B: numerator exp + segment sum
__global__ void edge_exp_kernel(const int* __restrict__ dst, float* __restrict__ elog,
                                const unsigned* __restrict__ maxenc, float* __restrict__ denom,
                                int E) {
    int i = blockIdx.x * blockDim.x + threadIdx.x;
    if (i >= E * NH) return;
    int e = i >> 2, h = i & 3;
    int t = dst[e];
    float m = fdec(maxenc[t * NH + h]);
    float a = expf(elog[i] - m);
    elog[i] = a;
    atomicAdd(&denom[t * NH + h], a);
}

// pass C: aggregate (head mean fused), 4 edges per 256-thread block,
// 64 threads per edge, each thread handles 4 consecutive d via one red.v4.f32
__global__ void aggregate_kernel(const int* __restrict__ src, const int* __restrict__ dst,
                                 const float* __restrict__ anum, const float* __restrict__ denom,
                                 const float* __restrict__ z, float* __restrict__ aggm, int E) {
    __shared__ float al[4][NH];
    __shared__ int sidx[4], tidx[4];
    int e0 = blockIdx.x * 4;
    int tid = threadIdx.x;
    if (tid < 16) {
        int le = tid >> 2, h = tid & 3;
        int e = e0 + le;
        if (e < E) {
            int t = dst[e];
            float dn = denom[t * NH + h];
            al[le][h] = anum[e * NH + h] / fmaxf(dn, 1e-9f) * 0.25f;
            if (h == 0) { sidx[le] = src[e]; tidx[le] = t; }
        }
    }
    __syncthreads();
    int le = tid >> 6, t64 = tid & 63;
    int e = e0 + le;
    if (e >= E) return;
    int s = sidx[le], t = tidx[le];
    const float4* zr = (const float4*)(z + (size_t)s * HDTOT);
    float4 v = make_float4(0.f, 0.f, 0.f, 0.f);
#pragma unroll
    for (int h = 0; h < NH; h++) {
        float a = al[le][h];
        float4 zv = zr[h * 64 + t64];
        v.x = fmaf(a, zv.x, v.x);
        v.y = fmaf(a, zv.y, v.y);
        v.z = fmaf(a, zv.z, v.z);
        v.w = fmaf(a, zv.w, v.w);
    }
    float* p = aggm + (size_t)t * HID + t64 * 4;
    asm volatile("red.global.add.v4.f32 [%0], {%1,%2,%3,%4};"
                 :: "l"(p), "f"(v.x), "f"(v.y), "f"(v.z), "f"(v.w) : "memory");
}

// ---------------- 3xTF32 tensor-core GEMM -------------------------------------
// C[M,N] = op( concat_k(A0|A1|A2)[M, nseg*256] @ B[nseg*256, N] (+addv) (+bias), relu? )
// A segments all have leading dim 256 (row-major). B row-major leading dim N.
#define FLAG_RELU 1

__device__ __forceinline__ void split_tf32(float x, uint32_t& hi, uint32_t& lo) {
    uint32_t h;
    asm("cvt.rna.tf32.f32 %0, %1;" : "=r"(h) : "f"(x));
    float r = x - __uint_as_float(h);
    uint32_t l;
    asm("cvt.rna.tf32.f32 %0, %1;" : "=r"(l) : "f"(r));
    hi = h; lo = l;
}

__device__ __forceinline__ void mma_tf32(float* c, const uint32_t* a, const uint32_t* b) {
    asm volatile(
        "mma.sync.aligned.m16n8k8.row.col.f32.tf32.tf32.f32 "
        "{%0,%1,%2,%3}, {%4,%5,%6,%7}, {%8,%9}, {%0,%1,%2,%3};"
        : "+f"(c[0]), "+f"(c[1]), "+f"(c[2]), "+f"(c[3])
        : "r"(a[0]), "r"(a[1]), "r"(a[2]), "r"(a[3]), "r"(b[0]), "r"(b[1]));
}

__global__ __launch_bounds__(256) void gemm_tf32(
    const float* __restrict__ A0, const float* __restrict__ A1p, const float* __restrict__ A2p,
    const float* __restrict__ B, float* __restrict__ C,
    int M, int N, int nseg,
    const float* __restrict__ addv, const float* __restrict__ bias, int flags) {
    __shared__ float As[128][20];   // [m][k] pad->stride 20: conflict-free frag loads
    __shared__ float Bs[16][136];   // [k][n] pad->stride 136

    int bm = blockIdx.y * 128, bn = blockIdx.x * 128;
    int tid = threadIdx.x;
    int w = tid >> 5, lane = tid & 31;
    int gid = lane >> 2, tig = lane & 3;
    int wm = (w >> 2) * 64, wn = (w & 3) * 32;  // warp tile 64x32, warps 2x4

    float acc[4][4][4];
#pragma unroll
    for (int i = 0; i < 4; i++)
#pragma unroll
        for (int j = 0; j < 4; j++)
#pragma unroll
            for (int q = 0; q < 4; q++) acc[i][j][q] = 0.f;

    int Ktot = nseg << 8;
    for (int k0 = 0; k0 < Ktot; k0 += 16) {
        const float* A = (k0 < 256) ? A0 : (k0 < 512 ? A1p : A2p);
        int kk = k0 & 255;
        // load A tile 128x16 (row-major in shared [m][k])
#pragma unroll
        for (int it = 0; it < 2; it++) {
            int idx = tid + it * 256;
            int row = idx >> 2, qc = (idx & 3) * 4;
            float4 v = make_float4(0.f, 0.f, 0.f, 0.f);
            int gr = bm + row;
            if (gr < M) v = *(const float4*)(A + (size_t)gr * 256 + kk + qc);
            *(float4*)&As[row][qc] = v;
        }
        // load B tile 16x128
#pragma unroll
        for (int it = 0; it < 2; it++) {
            int idx = tid + it * 256;
            int row = idx >> 5, nc = (idx & 31) * 4;
            float4 v = *(const float4*)(B + (size_t)(k0 + row) * N + bn + nc);
            *(float4*)&Bs[row][nc] = v;
        }
        __syncthreads();
#pragma unroll
        for (int ks = 0; ks < 16; ks += 8) {
            uint32_t ahi[4][4], alo[4][4], bhi[4][2], blo[4][2];
#pragma unroll
            for (int i = 0; i < 4; i++) {
                int r0 = wm + 16 * i + gid;
                split_tf32(As[r0][ks + tig],       ahi[i][0], alo[i][0]);
                split_tf32(As[r0 + 8][ks + tig],   ahi[i][1], alo[i][1]);
                split_tf32(As[r0][ks + tig + 4],   ahi[i][2], alo[i][2]);
                split_tf32(As[r0 + 8][ks + tig + 4], ahi[i][3], alo[i][3]);
            }
#pragma unroll
            for (int j = 0; j < 4; j++) {
                int c0 = wn + 8 * j + gid;
                split_tf32(Bs[ks + tig][c0],     bhi[j][0], blo[j][0]);
                split_tf32(Bs[ks + tig + 4][c0], bhi[j][1], blo[j][1]);
            }
#pragma unroll
            for (int i = 0; i < 4; i++)
#pragma unroll
                for (int j = 0; j < 4; j++) {
                    mma_tf32(acc[i][j], ahi[i], bhi[j]);
                    mma_tf32(acc[i][j], ahi[i], blo[j]);
                    mma_tf32(acc[i][j], alo[i], bhi[j]);
                }
        }
        __syncthreads();
    }

    // epilogue
#pragma unroll
    for (int i = 0; i < 4; i++) {
#pragma unroll
        for (int j = 0; j < 4; j++) {
            int r0 = bm + wm + 16 * i + gid;
            int r1 = r0 + 8;
            int c = bn + wn + 8 * j + 2 * tig;
            float2 v0 = make_float2(acc[i][j][0], acc[i][j][1]);
            float2 v1 = make_float2(acc[i][j][2], acc[i][j][3]);
            float bx = 0.f, by = 0.f;
            if (bias) { bx = bias[c]; by = bias[c + 1]; }
            if (r0 < M) {
                size_t idx = (size_t)r0 * N + c;
                if (addv) { v0.x += addv[idx]; v0.y += addv[idx + 1]; }
                v0.x += bx; v0.y += by;
                if (flags & FLAG_RELU) { v0.x = fmaxf(v0.x, 0.f); v0.y = fmaxf(v0.y, 0.f); }
                *(float2*)(C + idx) = v0;
            }
            if (r1 < M) {
                size_t idx = (size_t)r1 * N + c;
                if (addv) { v1.x += addv[idx]; v1.y += addv[idx + 1]; }
                v1.x += bx; v1.y += by;
                if (flags & FLAG_RELU) { v1.x = fmaxf(v1.x, 0.f); v1.y = fmaxf(v1.y, 0.f); }
                *(float2*)(C + idx) = v1;
            }
        }
    }
}

// final: out[n,0:2] = x1[n,:]@W2[256,2] + b2 ; warp per row
__global__ void final_kernel(const float* __restrict__ x1, const float* __restrict__ W2,
                             const float* __restrict__ b2, float* __restrict__ out, int N) {
    int warp = (blockIdx.x * blockDim.x + threadIdx.x) >> 5;
    int lane = threadIdx.x & 31;
    if (warp >= N) return;
    const float* xr = x1 + (size_t)warp * HID;
    float s0 = 0.f, s1 = 0.f;
    for (int k = lane; k < HID; k += 32) {
        float xv = xr[k];
        s0 = fmaf(xv, W2[k * 2 + 0], s0);
        s1 = fmaf(xv, W2[k * 2 + 1], s1);
    }
#pragma unroll
    for (int o = 16; o; o >>= 1) {
        s0 += __shfl_xor_sync(0xffffffffu, s0, o);
        s1 += __shfl_xor_sync(0xffffffffu, s1, o);
    }
    if (lane == 0) {
        out[warp * 2 + 0] = s0 + b2[0];
        out[warp * 2 + 1] = s1 + b2[1];
    }
}

// ---------------- host launcher ----------------------------------------------
static inline void* sym(const void* s) {
    void* p = nullptr;
    cudaGetSymbolAddress(&p, s);
    return p;
}

extern "C" void kernel_launch(void* const* d_in, const int* in_sizes, int n_in,
                              void* d_out, int out_size) {
    const float* x_link = (const float*)d_in[0];
    const float* x_flow = (const float*)d_in[1];
    const float* x_path = (const float*)d_in[2];
    const float* e2p = (const float*)d_in[3];
    const float* Wp_link = (const float*)d_in[4];
    const float* bp_link = (const float*)d_in[5];
    const float* Wp_flow = (const float*)d_in[6];
    const float* bp_flow = (const float*)d_in[7];
    const float* Wp_path = (const float*)d_in[8];
    const float* bp_path = (const float*)d_in[9];
    const float* fc_src1 = (const float*)d_in[10];
    const float* fc_dst1 = (const float*)d_in[11];
    const float* fc_e1 = (const float*)d_in[12];
    const float* attn_l1 = (const float*)d_in[13];
    const float* attn_r1 = (const float*)d_in[14];
    const float* attn_e1 = (const float*)d_in[15];
    const float* res_W1 = (const float*)d_in[16];
    const float* fc_src2 = (const float*)d_in[17];
    const float* fc_dst2 = (const float*)d_in[18];
    const float* attn_l2 = (const float*)d_in[19];
    const float* attn_r2 = (const float*)d_in[20];
    const float* res_W2 = (const float*)d_in[21];
    const float* W1 = (const float*)d_in[22];
    const float* b1 = (const float*)d_in[23];
    const float* W2 = (const float*)d_in[24];
    const float* b2 = (const float*)d_in[25];
    const int* src1 = (const int*)d_in[26];
    const int* dst1 = (const int*)d_in[27];
    const int* src2 = (const int*)d_in[28];
    const int* dst2 = (const int*)d_in[29];
    float* out = (float*)d_out;

    float* hlink = (float*)sym(g_hlink);
    float* hflow = (float*)sym(g_hflow);
    float* hp0 = (float*)sym(g_hp0);
    float* hp1 = (float*)sym(g_hp1);
    float* hp2 = (float*)sym(g_hp2);
    float* z = (float*)sym(g_z);
    float* aggm = (float*)sym(g_aggm);
    float* x1 = (float*)sym(g_x1);
    float* vl = (float*)sym(g_vl);
    float* vr = (float*)sym(g_vr);
    float* ce = (float*)sym(g_ce);
    float* el = (float*)sym(g_el);
    float* er = (float*)sym(g_er);
    float* elog = (float*)sym(g_elog);
    unsigned* maxenc = (unsigned*)sym(g_maxenc);
    float* denom = (float*)sym(g_denom);

    // 1) per-type projections
    proj_kernel<8><<<N_LINK, HID>>>(x_link, Wp_link, bp_link, hlink, N_LINK);
    proj_kernel<16><<<N_FLOW, HID>>>(x_flow, Wp_flow, bp_flow, hflow, N_FLOW);
    proj_kernel<8><<<N_PATH, HID>>>(x_path, Wp_path, bp_path, hp0, N_PATH);

    dim3 gz1(HDTOT / 128, (N_LINK + 127) / 128);
    dim3 gz2(HDTOT / 128, (N_FLOW + 127) / 128);
    dim3 gres(HID / 128, (N_PATH + 127) / 128);

    // ====================== conv1: link -> path ======================
    attnvec_kernel<<<HID, 128>>>(fc_src1, attn_l1, vl);
    attnvec_kernel<<<HID, 128>>>(fc_dst1, attn_r1, vr);
    attnvec_kernel<<<1, 128>>>(fc_e1, attn_e1, ce);

    gemm_tf32<<<gz1, 256>>>(hlink, nullptr, nullptr, fc_src1, z, N_LINK, HDTOT, 1,
                            nullptr, nullptr, 0);
    dotvec_kernel<<<N_LINK, 128>>>(hlink, vl, el, N_LINK);
    dotvec_kernel<<<N_PATH, 128>>>(hp0, vr, er, N_PATH);

    init_seg_kernel<<<(N_PATH * NH + 255) / 256, 256>>>(maxenc, denom, N_PATH * NH);
    cudaMemsetAsync(aggm, 0, (size_t)N_PATH * HID * sizeof(float));

    edge_logits_kernel<<<(E1 * NH + 255) / 256, 256>>>(src1, dst1, el, er, e2p, ce, elog, maxenc, E1, 1);
    edge_exp_kernel<<<(E1 * NH + 255) / 256, 256>>>(dst1, elog, maxenc, denom, E1);
    aggregate_kernel<<<(E1 + 3) / 4, 256>>>(src1, dst1, elog, denom, z, aggm, E1);

    // hp1 = relu(aggm + hp0 @ res_W1)
    gemm_tf32<<<gres, 256>>>(hp0, nullptr, nullptr, res_W1, hp1, N_PATH, HID, 1,
                             aggm, nullptr, FLAG_RELU);

    // ====================== conv2: flow -> path ======================
    attnvec_kernel<<<HID, 128>>>(fc_src2, attn_l2, vl);
    attnvec_kernel<<<HID, 128>>>(fc_dst2, attn_r2, vr);

    gemm_tf32<<<gz2, 256>>>(hflow, nullptr, nullptr, fc_src2, z, N_FLOW, HDTOT, 1,
                            nullptr, nullptr, 0);
    dotvec_kernel<<<N_FLOW, 128>>>(hflow, vl, el, N_FLOW);
    dotvec_kernel<<<N_PATH, 128>>>(hp1, vr, er, N_PATH);

    init_seg_kernel<<<(N_PATH * NH + 255) / 256, 256>>>(maxenc, denom, N_PATH * NH);
    cudaMemsetAsync(aggm, 0, (size_t)N_PATH * HID * sizeof(float));

    edge_logits_kernel<<<(E2 * NH + 255) / 256, 256>>>(src2, dst2, el, er, nullptr, ce, elog, maxenc, E2, 0);
    edge_exp_kernel<<<(E2 * NH + 255) / 256, 256>>>(dst2, elog, maxenc, denom, E2);
    aggregate_kernel<<<(E2 + 3) / 4, 256>>>(src2, dst2, elog, denom, z, aggm, E2);

    // hp2 = relu(aggm + hp1 @ res_W2)
    gemm_tf32<<<gres, 256>>>(hp1, nullptr, nullptr, res_W2, hp2, N_PATH, HID, 1,
                             aggm, nullptr, FLAG_RELU);

    // ====================== decoder ======================
    // x1 = relu(concat(hp2, hp1, hp2) @ W1 + b1) as ONE segmented K=768 GEMM
    gemm_tf32<<<gres, 256>>>(hp2, hp1, hp2, W1, x1, N_PATH, HID, 3,
                             nullptr, b1, FLAG_RELU);

    // out = x1 @ W2 + b2
    final_kernel<<<(N_PATH * 32 + 255) / 256, 256>>>(x1, W2, b2, out, N_PATH);
}